// round 4
// baseline (speedup 1.0000x reference)
#include <cuda_runtime.h>

// Tree shape: DEPTH=4, V=4.  n4=1, n3=5, n2=25, n1=125, n0=125.
#define NV   4
#define N1   125
#define N2   25
#define N3   5
#define NTHREADS 256

__device__ __forceinline__ float ex2f(float a) {
    float r;
    asm("ex2.approx.f32 %0, %1;" : "=f"(r) : "f"(a));
    return r;
}
__device__ __forceinline__ float lg2f(float a) {
    float r;
    asm("lg2.approx.f32 %0, %1;" : "=f"(r) : "f"(a));
    return r;
}

// Evaluate one level-1 node m:  f1 = lam0[m] + sum_v lam1[m,v] * x_v^pow1[m,v]
__device__ __forceinline__ float eval_f1(int m,
                                         const float2* __restrict__ s1,
                                         const float*  __restrict__ s0,
                                         const float lx0, const float lx1,
                                         const float lx2, const float lx3) {
    float f = s0[m];
    float2 a = s1[m * 4 + 0];
    float2 b = s1[m * 4 + 1];
    float2 c = s1[m * 4 + 2];
    float2 d = s1[m * 4 + 3];
    // 4 independent EX2s in flight, then a short FFMA chain.
    float e0 = ex2f(a.y * lx0);
    float e1 = ex2f(b.y * lx1);
    float e2 = ex2f(c.y * lx2);
    float e3 = ex2f(d.y * lx3);
    f = fmaf(a.x, e0, f);
    f = fmaf(b.x, e1, f);
    f = fmaf(c.x, e2, f);
    f = fmaf(d.x, e3, f);
    return f;
}

__global__ __launch_bounds__(NTHREADS)
void nested_formula_kernel(const float4* __restrict__ x,      // (B, 4) as float4
                           const float*  __restrict__ lam0,   // (125,)
                           const float*  __restrict__ lam1,   // (125,4)
                           const float*  __restrict__ pow1,
                           const float*  __restrict__ lam2,   // (25,4)
                           const float*  __restrict__ pow2,
                           const float*  __restrict__ lam3,   // (5,4)
                           const float*  __restrict__ pow3,
                           const float*  __restrict__ lam4,   // (1,4)
                           const float*  __restrict__ pow4,
                           float* __restrict__ out,           // (B,)
                           int B) {
    // Interleaved (lam, pow) parameter stage in shared memory (broadcast reads).
    __shared__ float2 s1[N1 * NV];   // 4000 B
    __shared__ float2 s2[N2 * NV];   //  800 B
    __shared__ float2 s3[N3 * NV];   //  160 B
    __shared__ float2 s4[NV];        //   32 B
    __shared__ float  s0[N1];        //  500 B

    const int tid = threadIdx.x;
    for (int i = tid; i < N1 * NV; i += NTHREADS)
        s1[i] = make_float2(lam1[i], pow1[i]);
    for (int i = tid; i < N2 * NV; i += NTHREADS)
        s2[i] = make_float2(lam2[i], pow2[i]);
    if (tid < N3 * NV) s3[tid] = make_float2(lam3[tid], pow3[tid]);
    if (tid < NV)      s4[tid] = make_float2(lam4[tid], pow4[tid]);
    if (tid < N1)      s0[tid] = lam0[tid];
    __syncthreads();

    const int b = blockIdx.x * NTHREADS + tid;
    if (b >= B) return;

    const float4 xv = x[b];   // coalesced 16B/thread
    const float lx0 = lg2f(xv.x);
    const float lx1 = lg2f(xv.y);
    const float lx2 = lg2f(xv.z);
    const float lx3 = lg2f(xv.w);
    const float lx[4] = {lx0, lx1, lx2, lx3};

    float acc4 = 0.0f;
    #pragma unroll 1
    for (int j = 0; j < 5; ++j) {          // 5 level-3 nodes (root's children)
        float acc3 = 0.0f;
        #pragma unroll 1
        for (int kk = 0; kk < 5; ++kk) {   // 5 level-2 children of node j
            const int k = j * 5 + kk;
            // level-2 node k: acc2 = sum_{mm<4} lam2*x^pow2*f1(k*5+mm) + f1(k*5+4)
            float acc2 = eval_f1(k * 5 + 4, s1, s0, lx0, lx1, lx2, lx3);
            #pragma unroll
            for (int mm = 0; mm < 4; ++mm) {
                const float  f1 = eval_f1(k * 5 + mm, s1, s0, lx0, lx1, lx2, lx3);
                const float2 lp = s2[k * 4 + mm];
                acc2 = fmaf(lp.x * ex2f(lp.y * lx[mm]), f1, acc2);
            }
            if (kk < 4) {
                const float2 lp = s3[j * 4 + kk];
                acc3 = fmaf(lp.x * ex2f(lp.y * lx[kk]), acc2, acc3);
            } else {
                acc3 += acc2;
            }
        }
        if (j < 4) {
            const float2 lp = s4[j];
            acc4 = fmaf(lp.x * ex2f(lp.y * lx[j]), acc3, acc4);
        } else {
            acc4 += acc3;
        }
    }

    out[b] = acc4;
}

extern "C" void kernel_launch(void* const* d_in, const int* in_sizes, int n_in,
                              void* d_out, int out_size) {
    // metadata order: x, lam0, lam1, pow1, lam2, pow2, lam3, pow3, lam4, pow4
    const float4* x    = (const float4*)d_in[0];
    const float*  lam0 = (const float*)d_in[1];
    const float*  lam1 = (const float*)d_in[2];
    const float*  pow1 = (const float*)d_in[3];
    const float*  lam2 = (const float*)d_in[4];
    const float*  pow2 = (const float*)d_in[5];
    const float*  lam3 = (const float*)d_in[6];
    const float*  pow3 = (const float*)d_in[7];
    const float*  lam4 = (const float*)d_in[8];
    const float*  pow4 = (const float*)d_in[9];
    float* out = (float*)d_out;

    const int B = in_sizes[0] / 4;   // x has B*4 elements
    const int grid = (B + NTHREADS - 1) / NTHREADS;
    nested_formula_kernel<<<grid, NTHREADS>>>(x, lam0, lam1, pow1, lam2, pow2,
                                              lam3, pow3, lam4, pow4, out, B);
}

// round 5
// speedup vs baseline: 1.0088x; 1.0088x over previous
#include <cuda_runtime.h>

// Tree shape: DEPTH=4, V=4.  n4=1, n3=5, n2=25, n1=125, n0=125.
#define NV   4
#define N1   125
#define N2   25
#define N3   5
#define NTHREADS 128   // 2 batch elements per thread -> 256 elems/block

__device__ __forceinline__ float ex2f(float a) {
    float r;
    asm("ex2.approx.f32 %0, %1;" : "=f"(r) : "f"(a));
    return r;
}
__device__ __forceinline__ float lg2f(float a) {
    float r;
    asm("lg2.approx.f32 %0, %1;" : "=f"(r) : "f"(a));
    return r;
}

// Level-1 node m evaluated for TWO batch elements at once.
// v1[2m]   = (lam_m0, pow_m0, lam_m1, pow_m1)
// v1[2m+1] = (lam_m2, pow_m2, lam_m3, pow_m3)
__device__ __forceinline__ void eval_f1_pair(
    const float4* __restrict__ v1, const float* __restrict__ s0, int m,
    float lxA0, float lxA1, float lxA2, float lxA3,
    float lxB0, float lxB1, float lxB2, float lxB3,
    float& fA, float& fB)
{
    const float4 q0 = v1[2 * m];
    const float4 q1 = v1[2 * m + 1];
    const float  s  = s0[m];
    // 8 independent EX2s in flight.
    const float eA0 = ex2f(q0.y * lxA0);
    const float eA1 = ex2f(q0.w * lxA1);
    const float eA2 = ex2f(q1.y * lxA2);
    const float eA3 = ex2f(q1.w * lxA3);
    const float eB0 = ex2f(q0.y * lxB0);
    const float eB1 = ex2f(q0.w * lxB1);
    const float eB2 = ex2f(q1.y * lxB2);
    const float eB3 = ex2f(q1.w * lxB3);
    fA = fmaf(q0.x, eA0, fmaf(q0.z, eA1, fmaf(q1.x, eA2, fmaf(q1.z, eA3, s))));
    fB = fmaf(q0.x, eB0, fmaf(q0.z, eB1, fmaf(q1.x, eB2, fmaf(q1.z, eB3, s))));
}

__global__ __launch_bounds__(NTHREADS)
void nested_formula_kernel(const float4* __restrict__ x,      // (B, 4) as float4
                           const float*  __restrict__ lam0,   // (125,)
                           const float*  __restrict__ lam1,   // (125,4)
                           const float*  __restrict__ pow1,
                           const float*  __restrict__ lam2,   // (25,4)
                           const float*  __restrict__ pow2,
                           const float*  __restrict__ lam3,   // (5,4)
                           const float*  __restrict__ pow3,
                           const float*  __restrict__ lam4,   // (1,4)
                           const float*  __restrict__ pow4,
                           float* __restrict__ out,           // (B,)
                           int B) {
    // Interleaved (lam, pow) parameter stage, 16B-aligned for LDS.128 reads.
    __shared__ __align__(16) float2 s1[N1 * NV];   // 4000 B
    __shared__ __align__(16) float2 s2[N2 * NV];   //  800 B
    __shared__ __align__(16) float2 s3[N3 * NV];   //  160 B
    __shared__ __align__(16) float2 s4[NV];        //   32 B
    __shared__ float  s0[N1];                      //  500 B

    const int tid = threadIdx.x;
    for (int i = tid; i < N1 * NV; i += NTHREADS)
        s1[i] = make_float2(lam1[i], pow1[i]);
    if (tid < N2 * NV) s2[tid] = make_float2(lam2[tid], pow2[tid]);
    if (tid < N3 * NV) s3[tid] = make_float2(lam3[tid], pow3[tid]);
    if (tid < NV)      s4[tid] = make_float2(lam4[tid], pow4[tid]);
    if (tid < N1)      s0[tid] = lam0[tid];
    __syncthreads();

    const float4* v1 = (const float4*)s1;
    const float4* v2 = (const float4*)s2;

    // Two batch elements per thread, coalesced: [b0 .. b0+127] and [+128 .. +255].
    const int b0 = blockIdx.x * (2 * NTHREADS) + tid;
    const int b1 = b0 + NTHREADS;

    const float4 xA = x[b0];
    const float4 xB = x[b1];
    const float lxA0 = lg2f(xA.x), lxA1 = lg2f(xA.y), lxA2 = lg2f(xA.z), lxA3 = lg2f(xA.w);
    const float lxB0 = lg2f(xB.x), lxB1 = lg2f(xB.y), lxB2 = lg2f(xB.z), lxB3 = lg2f(xB.w);

    float acc4A = 0.0f, acc4B = 0.0f;
    #pragma unroll 1
    for (int j = 0; j < 5; ++j) {          // 5 level-3 nodes (root's children)
        float acc3A = 0.0f, acc3B = 0.0f;
        #pragma unroll 1
        for (int kk = 0; kk < 5; ++kk) {   // 5 level-2 children of node j
            const int k = j * 5 + kk;
            // level-2 node k: acc2 = sum_{mm<4} lam2*x^pow2*f1(k*5+mm) + f1(k*5+4)
            float acc2A, acc2B;
            eval_f1_pair(v1, s0, k * 5 + 4,
                         lxA0, lxA1, lxA2, lxA3, lxB0, lxB1, lxB2, lxB3,
                         acc2A, acc2B);
            const float4 p0 = v2[2 * k];       // (lam_k0,pow_k0,lam_k1,pow_k1)
            const float4 p1 = v2[2 * k + 1];   // (lam_k2,pow_k2,lam_k3,pow_k3)
            {
                float fA, fB;
                eval_f1_pair(v1, s0, k * 5 + 0,
                             lxA0, lxA1, lxA2, lxA3, lxB0, lxB1, lxB2, lxB3, fA, fB);
                acc2A = fmaf(p0.x * ex2f(p0.y * lxA0), fA, acc2A);
                acc2B = fmaf(p0.x * ex2f(p0.y * lxB0), fB, acc2B);
            }
            {
                float fA, fB;
                eval_f1_pair(v1, s0, k * 5 + 1,
                             lxA0, lxA1, lxA2, lxA3, lxB0, lxB1, lxB2, lxB3, fA, fB);
                acc2A = fmaf(p0.z * ex2f(p0.w * lxA1), fA, acc2A);
                acc2B = fmaf(p0.z * ex2f(p0.w * lxB1), fB, acc2B);
            }
            {
                float fA, fB;
                eval_f1_pair(v1, s0, k * 5 + 2,
                             lxA0, lxA1, lxA2, lxA3, lxB0, lxB1, lxB2, lxB3, fA, fB);
                acc2A = fmaf(p1.x * ex2f(p1.y * lxA2), fA, acc2A);
                acc2B = fmaf(p1.x * ex2f(p1.y * lxB2), fB, acc2B);
            }
            {
                float fA, fB;
                eval_f1_pair(v1, s0, k * 5 + 3,
                             lxA0, lxA1, lxA2, lxA3, lxB0, lxB1, lxB2, lxB3, fA, fB);
                acc2A = fmaf(p1.z * ex2f(p1.w * lxA3), fA, acc2A);
                acc2B = fmaf(p1.z * ex2f(p1.w * lxB3), fB, acc2B);
            }
            if (kk < 4) {
                // select lx_kk without a dynamically-indexed array (no local mem)
                const float lxkA = (kk == 0) ? lxA0 : (kk == 1) ? lxA1 : (kk == 2) ? lxA2 : lxA3;
                const float lxkB = (kk == 0) ? lxB0 : (kk == 1) ? lxB1 : (kk == 2) ? lxB2 : lxB3;
                const float2 lp = s3[j * 4 + kk];
                acc3A = fmaf(lp.x * ex2f(lp.y * lxkA), acc2A, acc3A);
                acc3B = fmaf(lp.x * ex2f(lp.y * lxkB), acc2B, acc3B);
            } else {
                acc3A += acc2A;
                acc3B += acc2B;
            }
        }
        if (j < 4) {
            const float lxjA = (j == 0) ? lxA0 : (j == 1) ? lxA1 : (j == 2) ? lxA2 : lxA3;
            const float lxjB = (j == 0) ? lxB0 : (j == 1) ? lxB1 : (j == 2) ? lxB2 : lxB3;
            const float2 lp = s4[j];
            acc4A = fmaf(lp.x * ex2f(lp.y * lxjA), acc3A, acc4A);
            acc4B = fmaf(lp.x * ex2f(lp.y * lxjB), acc3B, acc4B);
        } else {
            acc4A += acc3A;
            acc4B += acc3B;
        }
    }

    out[b0] = acc4A;
    out[b1] = acc4B;
}

extern "C" void kernel_launch(void* const* d_in, const int* in_sizes, int n_in,
                              void* d_out, int out_size) {
    // metadata order: x, lam0, lam1, pow1, lam2, pow2, lam3, pow3, lam4, pow4
    const float4* x    = (const float4*)d_in[0];
    const float*  lam0 = (const float*)d_in[1];
    const float*  lam1 = (const float*)d_in[2];
    const float*  pow1 = (const float*)d_in[3];
    const float*  lam2 = (const float*)d_in[4];
    const float*  pow2 = (const float*)d_in[5];
    const float*  lam3 = (const float*)d_in[6];
    const float*  pow3 = (const float*)d_in[7];
    const float*  lam4 = (const float*)d_in[8];
    const float*  pow4 = (const float*)d_in[9];
    float* out = (float*)d_out;

    const int B = in_sizes[0] / 4;                 // x has B*4 elements
    const int elemsPerBlock = 2 * NTHREADS;        // 256
    const int grid = (B + elemsPerBlock - 1) / elemsPerBlock;
    nested_formula_kernel<<<grid, NTHREADS>>>(x, lam0, lam1, pow1, lam2, pow2,
                                              lam3, pow3, lam4, pow4, out, B);
}